// round 10
// baseline (speedup 1.0000x reference)
#include <cuda_runtime.h>

#define NTHREADS 256
#define MAX_BLOCKS 8192

#define C_PER_SAMPLE 7.1624450756f  // prior+lik constants per sample
#define C_ENTROPY    5.6757541328f  // 0.5*4*(1+log 2pi)

// ---------------- packed f32x2 helpers ----------------
union F2 { float2 f; unsigned long long u; };
union F4 { float4 v; F2 h[2]; };

__device__ __forceinline__ F2 mk2(float a, float b) { F2 r; r.f.x = a; r.f.y = b; return r; }
__device__ __forceinline__ F2 fma2(F2 a, F2 b, F2 c) {
    F2 d; asm("fma.rn.f32x2 %0, %1, %2, %3;" : "=l"(d.u) : "l"(a.u), "l"(b.u), "l"(c.u)); return d;
}
__device__ __forceinline__ F2 relu2(F2 a) {
    F2 r; r.f.x = fmaxf(a.f.x, 0.0f); r.f.y = fmaxf(a.f.y, 0.0f); return r;
}

// ---------------- weight layouts (all duplicated {w,w} for packed FMA) ------
struct WPack {                    // constant port (LDC)
    float4 l1a[3][10];            // {W1[0][2jp]x2, W1[0][2jp+1]x2}
    float4 l1b[3][10];            // {W1[1][2jp]x2, ...}
    float4 l1c[3][10];            // {b1[2jp]x2, ...}
    float4 w3d[3][6][5];          // {W3[2q][o]x2, W3[2q+1][o]x2} (pads 0)
    float4 b2d[3][5];             // {b2[2t]x2, b2[2t+1]x2}
    float2 b3d[3][6];             // {b3[o], b3[o]}
};
// layer-2 weights -> per-block smem (LDS.128 broadcast, floor 4 < LDC floor 8)
struct W2Glob { float4 w2d[3][20][5]; };   // {W2[j][2t]x2, W2[j][2t+1]x2}

__constant__ WPack c_w;
__device__   WPack g_stage;
__device__   W2Glob g_w2d;
__device__ double g_partial[MAX_BLOCKS];
__device__ unsigned int g_ticket;   // zero-init; last block resets (graph-replay safe)

// ---------------------------------------------------------------------------
__global__ void pack_kernel(
    const float* mW1, const float* mb1, const float* mW2, const float* mb2,
    const float* mW3, const float* mb3,
    const float* dW1, const float* db1, const float* dW2, const float* db2,
    const float* dW3, const float* db3,
    const float* oW1, const float* ob1, const float* oW2, const float* ob2,
    const float* oW3, const float* ob3)
{
    const float* W1[3] = {mW1, dW1, oW1};
    const float* B1[3] = {mb1, db1, ob1};
    const float* W2[3] = {mW2, dW2, oW2};
    const float* B2[3] = {mb2, db2, ob2};
    const float* W3[3] = {mW3, dW3, oW3};
    const float* B3[3] = {mb3, db3, ob3};
    const int OUT[3] = {4, 4, 6};
    int t = threadIdx.x;

    for (int i = t; i < 30; i += blockDim.x) {          // layer1 duplicated
        int m = i / 10, jp = i % 10, j = 2 * jp;
        float a0 = W1[m][j],      a1 = W1[m][j + 1];
        float b0 = W1[m][20 + j], b1 = W1[m][20 + j + 1];
        float c0 = B1[m][j],      c1 = B1[m][j + 1];
        g_stage.l1a[m][jp] = make_float4(a0, a0, a1, a1);
        g_stage.l1b[m][jp] = make_float4(b0, b0, b1, b1);
        g_stage.l1c[m][jp] = make_float4(c0, c0, c1, c1);
    }
    for (int i = t; i < 300; i += blockDim.x) {         // layer2 duplicated
        int m = i / 100, r = i % 100, j = r / 5, tt = r % 5;
        float w0 = W2[m][j * 10 + 2 * tt];
        float w1 = W2[m][j * 10 + 2 * tt + 1];
        g_w2d.w2d[m][j][tt] = make_float4(w0, w0, w1, w1);
    }
    for (int i = t; i < 90; i += blockDim.x) {          // layer3 duplicated
        int m = i / 30, r = i % 30, o = r / 5, q = r % 5;
        int Om = OUT[m];
        int k0 = 2 * q, k1 = 2 * q + 1;
        float w0 = (o < Om && k0 < 10) ? W3[m][k0 * Om + o] : 0.0f;
        float w1 = (o < Om && k1 < 10) ? W3[m][k1 * Om + o] : 0.0f;
        g_stage.w3d[m][o][q] = make_float4(w0, w0, w1, w1);
    }
    for (int i = t; i < 15; i += blockDim.x) {          // b2 duplicated
        int m = i / 5, tt = i % 5;
        float b0 = B2[m][2 * tt], b1 = B2[m][2 * tt + 1];
        g_stage.b2d[m][tt] = make_float4(b0, b0, b1, b1);
    }
    for (int i = t; i < 18; i += blockDim.x) {          // b3 duplicated
        int m = i / 6, o = i % 6;
        float b = (o < OUT[m]) ? B3[m][o] : 0.0f;
        g_stage.b3d[m][o] = make_float2(b, b);
    }
}

// ---------------------------------------------------------------------------
// Fully packed 2-row MLP, j-streaming (no h array). sw2: smem layer-2 base
// for this net. Outputs: F2 per output unit, lanes = {rowA, rowB}.
template <int M, int OUT>
__device__ __forceinline__ void mlp2(const float4* __restrict__ sw2,
                                     F2 y0d, F2 y1d, F2* out)
{
    F2 acc[10];
#pragma unroll
    for (int tt = 0; tt < 5; tt++) {
        F4 b; b.v = c_w.b2d[M][tt];
        acc[2 * tt]     = b.h[0];
        acc[2 * tt + 1] = b.h[1];
    }
#pragma unroll
    for (int jp = 0; jp < 10; jp++) {
        F4 wa, wb, wc;
        wa.v = c_w.l1a[M][jp];
        wb.v = c_w.l1b[M][jp];
        wc.v = c_w.l1c[M][jp];
        F2 h0 = relu2(fma2(wa.h[0], y0d, fma2(wb.h[0], y1d, wc.h[0])));
        F2 h1 = relu2(fma2(wa.h[1], y0d, fma2(wb.h[1], y1d, wc.h[1])));
        const float4* w0 = sw2 + (2 * jp) * 5;
        const float4* w1 = sw2 + (2 * jp + 1) * 5;
#pragma unroll
        for (int tt = 0; tt < 5; tt++) {
            F4 u0; u0.v = w0[tt];
            acc[2 * tt]     = fma2(u0.h[0], h0, acc[2 * tt]);
            acc[2 * tt + 1] = fma2(u0.h[1], h0, acc[2 * tt + 1]);
            F4 u1; u1.v = w1[tt];
            acc[2 * tt]     = fma2(u1.h[0], h1, acc[2 * tt]);
            acc[2 * tt + 1] = fma2(u1.h[1], h1, acc[2 * tt + 1]);
        }
    }
#pragma unroll
    for (int k = 0; k < 10; k++) acc[k] = relu2(acc[k]);
#pragma unroll
    for (int o = 0; o < OUT; o++) {
        F2 s; s.f = c_w.b3d[M][o];
#pragma unroll
        for (int q = 0; q < 5; q++) {
            F4 w; w.v = c_w.w3d[M][o][q];
            s = fma2(w.h[0], acc[2 * q], s);
            s = fma2(w.h[1], acc[2 * q + 1], s);
        }
        out[o] = s;
    }
}

__device__ __forceinline__ float softplus_f(float x)
{
    return fmaxf(x, 0.0f) + __logf(1.0f + __expf(-fabsf(x)));
}

// Scalar per-row sample term (known-good from R9).
__device__ __forceinline__ float sample_term(
    const float4 z, const F2* mu, const F2* off, int lane,
    float d0, float d1, float d2, float d3, float yx100, float yy100)
{
    float m0 = lane ? mu[0].f.y : mu[0].f.x;
    float m1 = lane ? mu[1].f.y : mu[1].f.x;
    float m2 = lane ? mu[2].f.y : mu[2].f.x;
    float m3 = lane ? mu[3].f.y : mu[3].f.x;
    float o0 = lane ? off[0].f.y : off[0].f.x;
    float o1 = lane ? off[1].f.y : off[1].f.x;
    float o2 = lane ? off[2].f.y : off[2].f.x;
    float o3 = lane ? off[3].f.y : off[3].f.x;
    float o4 = lane ? off[4].f.y : off[4].f.x;
    float o5 = lane ? off[5].f.y : off[5].f.x;

    float xi0 = fmaf(d0, z.x, m0);
    float xi1 = fmaf(d1, z.y, fmaf(o0, z.x, m1));
    float xi2 = fmaf(d2, z.z, fmaf(o2, z.y, fmaf(o1, z.x, m2)));
    float xi3 = fmaf(d3, z.w, fmaf(o5, z.z, fmaf(o4, z.y, fmaf(o3, z.x, m3))));

    float a2 = xi1 + xi2;
    float a3 = a2 + xi3;
    float s1, c1, s2, c2, s3, c3;
    __sincosf(xi1, &s1, &c1);
    __sincosf(a2,  &s2, &c2);
    __sincosf(a3,  &s3, &c3);

    float px = fmaf(0.5f, c1, fmaf(0.5f, c2, c3));
    float py = xi0 + fmaf(0.5f, s1, fmaf(0.5f, s2, s3));

    float rx = fmaf(-100.0f, px, yx100);
    float ry = fmaf(-100.0f, py, yy100);

    float s123 = fmaf(xi1, xi1, fmaf(xi2, xi2, xi3 * xi3));
    float tq = fmaf(xi0 * -8.0f, xi0, -2.0f * s123);
    float r2 = fmaf(rx, rx, ry * ry);
    return fmaf(-0.5f, r2, tq);
}

// ---------------------------------------------------------------------------
__global__ void __launch_bounds__(NTHREADS, 4)
vi_kernel(const float* __restrict__ y, const float* __restrict__ zs, int N,
          float* __restrict__ out)
{
    __shared__ float4 s_w2[300];     // 3 nets x 20 j x 5
    __shared__ double sred[NTHREADS];
    __shared__ float wsum[NTHREADS / 32];
    __shared__ int sh_last;

    int tid = threadIdx.x;
    {
        const float4* src = (const float4*)&g_w2d;
        for (int i = tid; i < 300; i += NTHREADS) s_w2[i] = __ldg(&src[i]);
    }
    __syncthreads();

    int g = blockIdx.x * NTHREADS + tid;
    int n0 = 2 * g, n1 = n0 + 1;
    float val = 0.0f;

    if (n0 < N) {
        bool two = (n1 < N);
        float4 yv;
        if (two) {
            yv = ((const float4*)y)[g];
        } else {
            float2 ya = ((const float2*)y)[n0];
            yv = make_float4(ya.x, ya.y, ya.x, ya.y);
            n1 = n0;
        }
        F2 y0d = mk2(yv.x, yv.z);
        F2 y1d = mk2(yv.y, yv.w);

        const float4* zpA = (const float4*)zs + (size_t)n0 * 8;
        const float4* zpB = (const float4*)zs + (size_t)n1 * 8;
        float4 zA = zpA[0];          // prefetch; hides under MLP block
        float4 zB = zpB[0];

        F2 mu[4], ldr[4], off[6];
        mlp2<0, 4>(s_w2 +   0, y0d, y1d, mu);
        mlp2<1, 4>(s_w2 + 100, y0d, y1d, ldr);
        mlp2<2, 6>(s_w2 + 200, y0d, y1d, off);

        float d0A = softplus_f(ldr[0].f.x), d0B = softplus_f(ldr[0].f.y);
        float d1A = softplus_f(ldr[1].f.x), d1B = softplus_f(ldr[1].f.y);
        float d2A = softplus_f(ldr[2].f.x), d2B = softplus_f(ldr[2].f.y);
        float d3A = softplus_f(ldr[3].f.x), d3B = softplus_f(ldr[3].f.y);

        float yxA = yv.x * 100.0f, yyA = yv.y * 100.0f;
        float yxB = yv.z * 100.0f, yyB = yv.w * 100.0f;

        float accA = 0.0f, accB = 0.0f;
#pragma unroll
        for (int p = 0; p < 8; p++) {
            float4 za = zA, zb = zB;
            if (p < 7) { zA = zpA[p + 1]; zB = zpB[p + 1]; }
            accA += sample_term(za, mu, off, 0, d0A, d1A, d2A, d3A, yxA, yyA);
            accB += sample_term(zb, mu, off, 1, d0B, d1B, d2B, d3B, yxB, yyB);
        }

        float vA = fmaf(accA, 0.125f, C_PER_SAMPLE) + C_ENTROPY +
                   __logf(d0A * d1A * d2A * d3A);
        float vB = fmaf(accB, 0.125f, C_PER_SAMPLE) + C_ENTROPY +
                   __logf(d0B * d1B * d2B * d3B);
        val = two ? (vA + vB) : vA;
    }

    // ---- deterministic block reduction ----
#pragma unroll
    for (int o = 16; o > 0; o >>= 1)
        val += __shfl_down_sync(0xffffffffu, val, o);
    if ((tid & 31) == 0) wsum[tid >> 5] = val;
    __syncthreads();
    if (tid == 0) {
        double s = 0.0;
#pragma unroll
        for (int w = 0; w < NTHREADS / 32; w++) s += (double)wsum[w];
        g_partial[blockIdx.x] = s;
        __threadfence();
        unsigned t = atomicAdd(&g_ticket, 1u);
        sh_last = (t == gridDim.x - 1) ? 1 : 0;
    }
    __syncthreads();

    // ---- fused finalize: last block reduces partials deterministically ----
    if (sh_last) {
        __threadfence();
        double s = 0.0;
        for (int i = tid; i < (int)gridDim.x; i += NTHREADS)
            s += __ldcg(&g_partial[i]);
        sred[tid] = s;
        __syncthreads();
#pragma unroll
        for (int st = NTHREADS / 2; st > 0; st >>= 1) {
            if (tid < st) sred[tid] += sred[tid + st];
            __syncthreads();
        }
        if (tid == 0) {
            out[0] = (float)(sred[0] / (double)N);
            __threadfence();
            g_ticket = 0;   // reset for next graph replay
        }
    }
}

// ---------------------------------------------------------------------------
extern "C" void kernel_launch(void* const* d_in, const int* in_sizes, int n_in,
                              void* d_out, int out_size)
{
    const float* y  = (const float*)d_in[0];
    const float* zs = (const float*)d_in[1];
    int N = in_sizes[0] / 2;
    int npairs = (N + 1) / 2;
    int nblocks = (npairs + NTHREADS - 1) / NTHREADS;
    if (nblocks > MAX_BLOCKS) nblocks = MAX_BLOCKS;

    pack_kernel<<<1, 128>>>(
        (const float*)d_in[2],  (const float*)d_in[3],  (const float*)d_in[4],
        (const float*)d_in[5],  (const float*)d_in[6],  (const float*)d_in[7],
        (const float*)d_in[8],  (const float*)d_in[9],  (const float*)d_in[10],
        (const float*)d_in[11], (const float*)d_in[12], (const float*)d_in[13],
        (const float*)d_in[14], (const float*)d_in[15], (const float*)d_in[16],
        (const float*)d_in[17], (const float*)d_in[18], (const float*)d_in[19]);

    void* caddr = nullptr;
    void* saddr = nullptr;
    cudaGetSymbolAddress(&caddr, c_w);
    cudaGetSymbolAddress(&saddr, g_stage);
    cudaMemcpyAsync(caddr, saddr, sizeof(WPack), cudaMemcpyDeviceToDevice, 0);

    vi_kernel<<<nblocks, NTHREADS>>>(y, zs, N, (float*)d_out);
}